// round 2
// baseline (speedup 1.0000x reference)
#include <cuda_runtime.h>
#include <math.h>

// Problem constants
#define DIMD  1024
#define ADIMD 256
#define HIDD  4096
#define NTOK  4096
#define NB    4
#define MROWS (NB * NTOK)        // 16384
#define DEPTH 4
#define SCALE_A 0.25f            // 16^-0.5

// ---------------- scratch (device globals; no allocation allowed) ----------
__device__ float g_h  [(size_t)MROWS * DIMD];    // 64 MB
__device__ float g_q  [(size_t)MROWS * ADIMD];   // 16 MB
__device__ float g_k  [(size_t)MROWS * ADIMD];   // 16 MB
__device__ float g_att[(size_t)MROWS * ADIMD];   // 16 MB
__device__ float g_hid[(size_t)MROWS * HIDD];    // 256 MB
__device__ float g_a  [MROWS];
__device__ float g_rn [NB];
__device__ float g_G  [NB * ADIMD];

// ---------------- reductions ----------------
__device__ __forceinline__ float warpSum(float v) {
#pragma unroll
    for (int o = 16; o > 0; o >>= 1) v += __shfl_xor_sync(0xFFFFFFFFu, v, o);
    return v;
}

// ---------------- LayerNorm: one row (1024) per block of 256 threads -------
__global__ void ln_kernel(const float* __restrict__ x,
                          const float* __restrict__ g,
                          const float* __restrict__ b,
                          float* __restrict__ out) {
    int row = blockIdx.x;
    const float* xr = x + (size_t)row * DIMD;
    float v[4];
    float s = 0.f, s2 = 0.f;
#pragma unroll
    for (int j = 0; j < 4; j++) {
        v[j] = xr[threadIdx.x + 256 * j];
        s += v[j];
        s2 += v[j] * v[j];
    }
    __shared__ float sh[2][8];
    s = warpSum(s); s2 = warpSum(s2);
    int w = threadIdx.x >> 5, l = threadIdx.x & 31;
    if (l == 0) { sh[0][w] = s; sh[1][w] = s2; }
    __syncthreads();
    if (w == 0) {
        float a = (l < 8) ? sh[0][l] : 0.f;
        float c = (l < 8) ? sh[1][l] : 0.f;
        a = warpSum(a); c = warpSum(c);
        if (l == 0) { sh[0][0] = a; sh[1][0] = c; }
    }
    __syncthreads();
    float mu  = sh[0][0] * (1.f / DIMD);
    float var = sh[1][0] * (1.f / DIMD) - mu * mu;
    float rs  = rsqrtf(var + 1e-6f);
    float* orow = out + (size_t)row * DIMD;
#pragma unroll
    for (int j = 0; j < 4; j++) {
        int c = threadIdx.x + 256 * j;
        orow[c] = (v[j] - mu) * rs * g[c] + b[c];
    }
}

// ---------------- SGEMM 128x128x8, 8x8 per thread, 256 threads -------------
// EPI: 0 = C = AB + bias
//      1 = C += AB + bias         (read-modify-write C)
//      2 = C = gelu(AB + bias)    (exact erf gelu)
//      3 = C = AB + bias + D      (D same shape as C)
template <int EPI>
__global__ __launch_bounds__(256)
void sgemm128(int M, int N, int K,
              const float* __restrict__ A,
              const float* __restrict__ B,
              const float* __restrict__ bias,
              const float* __restrict__ D,
              float* __restrict__ C) {
    __shared__ __align__(16) float As[8][128];
    __shared__ __align__(16) float Bs[8][128];

    const int bx = blockIdx.x;          // N tile
    const int by = blockIdx.y;          // M tile
    const int tid = threadIdx.x;
    const int tx = tid & 15;            // 16 cols of threads
    const int ty = tid >> 4;            // 16 rows of threads

    const float* Ab = A + (size_t)by * 128 * K;
    const float* Bb = B + bx * 128;

    const int arow = tid >> 1, acol = (tid & 1) * 4;
    const int brow = tid >> 5, bcol = (tid & 31) * 4;

    float acc[8][8];
#pragma unroll
    for (int i = 0; i < 8; i++)
#pragma unroll
        for (int j = 0; j < 8; j++) acc[i][j] = 0.f;

    for (int k0 = 0; k0 < K; k0 += 8) {
        float4 a4 = *(const float4*)(Ab + (size_t)arow * K + k0 + acol);
        As[acol + 0][arow] = a4.x;
        As[acol + 1][arow] = a4.y;
        As[acol + 2][arow] = a4.z;
        As[acol + 3][arow] = a4.w;
        float4 b4 = *(const float4*)(Bb + (size_t)(k0 + brow) * N + bcol);
        *(float4*)&Bs[brow][bcol] = b4;
        __syncthreads();
#pragma unroll
        for (int k = 0; k < 8; k++) {
            float ar[8], br[8];
#pragma unroll
            for (int i = 0; i < 8; i++) ar[i] = As[k][ty * 8 + i];
#pragma unroll
            for (int j = 0; j < 8; j++) br[j] = Bs[k][tx * 8 + j];
#pragma unroll
            for (int i = 0; i < 8; i++)
#pragma unroll
                for (int j = 0; j < 8; j++)
                    acc[i][j] += ar[i] * br[j];
        }
        __syncthreads();
    }

    const int colbase = bx * 128 + tx * 8;
    float bv[8];
#pragma unroll
    for (int j = 0; j < 8; j++) bv[j] = bias[colbase + j];

#pragma unroll
    for (int i = 0; i < 8; i++) {
        int row = by * 128 + ty * 8 + i;
        float* Crow = C + (size_t)row * N + colbase;
        float o[8];
#pragma unroll
        for (int j = 0; j < 8; j++) {
            float v = acc[i][j] + bv[j];
            if (EPI == 1) v += Crow[j];
            if (EPI == 2) v = 0.5f * v * (1.0f + erff(v * 0.70710678118654752f));
            if (EPI == 3) v += (D + (size_t)row * N + colbase)[j];
            o[j] = v;
        }
        float4* Cv = (float4*)Crow;
        Cv[0] = make_float4(o[0], o[1], o[2], o[3]);
        Cv[1] = make_float4(o[4], o[5], o[6], o[7]);
    }
}

// ---------------- L2-normalize each 256-wide row (one warp per row) --------
__global__ void rownorm_kernel(float* __restrict__ q) {
    int row  = blockIdx.x * 8 + (threadIdx.x >> 5);
    int lane = threadIdx.x & 31;
    float4* r = (float4*)(q + (size_t)row * ADIMD);
    float4 v0 = r[lane];
    float4 v1 = r[lane + 32];
    float s = v0.x * v0.x + v0.y * v0.y + v0.z * v0.z + v0.w * v0.w
            + v1.x * v1.x + v1.y * v1.y + v1.z * v1.z + v1.w * v1.w;
    s = warpSum(s);
    float inv = 1.0f / fmaxf(sqrtf(s), 1e-12f);
    v0.x *= inv; v0.y *= inv; v0.z *= inv; v0.w *= inv;
    v1.x *= inv; v1.y *= inv; v1.z *= inv; v1.w *= inv;
    r[lane]      = v0;
    r[lane + 32] = v1;
}

// ---------------- a[row] = SCALE * dot(q[row,:], wg) ----------------------
__global__ void adot_kernel(const float* __restrict__ q,
                            const float* __restrict__ wg,
                            float* __restrict__ a) {
    int row  = blockIdx.x * 8 + (threadIdx.x >> 5);
    int lane = threadIdx.x & 31;
    const float4* r = (const float4*)(q + (size_t)row * ADIMD);
    const float4* w = (const float4*)wg;
    float4 v0 = r[lane],     w0 = w[lane];
    float4 v1 = r[lane + 32], w1 = w[lane + 32];
    float s = v0.x * w0.x + v0.y * w0.y + v0.z * w0.z + v0.w * w0.w
            + v1.x * w1.x + v1.y * w1.y + v1.z * w1.z + v1.w * w1.w;
    s = warpSum(s);
    if (lane == 0) a[row] = s * SCALE_A;
}

// ---------------- per-batch 1/||a|| over 4096 tokens ----------------------
__global__ void anorm_kernel(const float* __restrict__ a, float* __restrict__ rn) {
    int b = blockIdx.x;
    float s = 0.f;
    for (int n = threadIdx.x; n < NTOK; n += 256) {
        float v = a[b * NTOK + n];
        s += v * v;
    }
    __shared__ float sh[8];
    s = warpSum(s);
    int w = threadIdx.x >> 5, l = threadIdx.x & 31;
    if (l == 0) sh[w] = s;
    __syncthreads();
    if (w == 0) {
        float v = (l < 8) ? sh[l] : 0.f;
        v = warpSum(v);
        if (l == 0) rn[b] = 1.0f / fmaxf(sqrtf(v), 1e-12f);
    }
}

// ---------------- G[b,c] = rn[b] * sum_n a[b,n] * q[b,n,c] ----------------
__global__ void gsum_kernel(const float* __restrict__ q,
                            const float* __restrict__ a,
                            const float* __restrict__ rn,
                            float* __restrict__ G) {
    int b = blockIdx.x;
    int c = threadIdx.x;
    const float* qb = q + (size_t)b * NTOK * ADIMD;
    const float* ab = a + b * NTOK;
    float s = 0.f;
#pragma unroll 8
    for (int n = 0; n < NTOK; n++)
        s += ab[n] * qb[(size_t)n * ADIMD + c];
    G[b * ADIMD + c] = s * rn[b];
}

// ---------------- k[b,n,c] *= G[b,c] --------------------------------------
__global__ void kscale_kernel(float* __restrict__ k, const float* __restrict__ G) {
    int idx = blockIdx.x * 1024 + threadIdx.x;     // 4M elements, 2^20 per batch
    int b = idx >> 20;
    int c = idx & 255;
    k[idx] *= G[b * ADIMD + c];
}

// ---------------- host orchestration --------------------------------------
extern "C" void kernel_launch(void* const* d_in, const int* in_sizes, int n_in,
                              void* d_out, int out_size) {
    const float* x_in  = (const float*)d_in[0];
    const float* ln1_g = (const float*)d_in[1];
    const float* ln1_b = (const float*)d_in[2];
    const float* Wq    = (const float*)d_in[3];
    const float* bq    = (const float*)d_in[4];
    const float* Wk    = (const float*)d_in[5];
    const float* bk    = (const float*)d_in[6];
    const float* w_g   = (const float*)d_in[7];
    const float* Wp    = (const float*)d_in[8];
    const float* bp    = (const float*)d_in[9];
    const float* Wf    = (const float*)d_in[10];
    const float* bf    = (const float*)d_in[11];
    const float* ln2_g = (const float*)d_in[12];
    const float* ln2_b = (const float*)d_in[13];
    const float* W1    = (const float*)d_in[14];
    const float* b1    = (const float*)d_in[15];
    const float* W2    = (const float*)d_in[16];
    const float* b2    = (const float*)d_in[17];

    float* x = (float*)d_out;   // residual stream lives in the output buffer

    void* p;
    cudaGetSymbolAddress(&p, g_h);   float* h   = (float*)p;
    cudaGetSymbolAddress(&p, g_q);   float* q   = (float*)p;
    cudaGetSymbolAddress(&p, g_k);   float* k   = (float*)p;
    cudaGetSymbolAddress(&p, g_att); float* att = (float*)p;
    cudaGetSymbolAddress(&p, g_hid); float* hid = (float*)p;
    cudaGetSymbolAddress(&p, g_a);   float* a   = (float*)p;
    cudaGetSymbolAddress(&p, g_rn);  float* rn  = (float*)p;
    cudaGetSymbolAddress(&p, g_G);   float* G   = (float*)p;

    cudaMemcpyAsync(x, x_in, sizeof(float) * (size_t)MROWS * DIMD,
                    cudaMemcpyDeviceToDevice);

    const dim3 gQK (ADIMD / 128, MROWS / 128);   // N=256
    const dim3 gDIM(DIMD  / 128, MROWS / 128);   // N=1024
    const dim3 gHID(HIDD  / 128, MROWS / 128);   // N=4096

    for (int i = 0; i < DEPTH; i++) {
        const float* Wq_i = Wq + (size_t)i * DIMD * ADIMD;
        const float* Wk_i = Wk + (size_t)i * DIMD * ADIMD;
        const float* Wp_i = Wp + (size_t)i * ADIMD * ADIMD;
        const float* Wf_i = Wf + (size_t)i * ADIMD * DIMD;
        const float* W1_i = W1 + (size_t)i * DIMD * HIDD;
        const float* W2_i = W2 + (size_t)i * HIDD * DIMD;

        // h = LN1(x)
        ln_kernel<<<MROWS, 256>>>(x, ln1_g + i * DIMD, ln1_b + i * DIMD, h);
        // q = h@Wq + bq ; k = h@Wk + bk
        sgemm128<0><<<gQK, 256>>>(MROWS, ADIMD, DIMD, h, Wq_i, bq + i * ADIMD, nullptr, q);
        sgemm128<0><<<gQK, 256>>>(MROWS, ADIMD, DIMD, h, Wk_i, bk + i * ADIMD, nullptr, k);
        // row-wise l2norm
        rownorm_kernel<<<MROWS / 8, 256>>>(q);
        rownorm_kernel<<<MROWS / 8, 256>>>(k);
        // a = SCALE * q @ w_g ; per-batch normalize ; G = sum_n a*q
        adot_kernel<<<MROWS / 8, 256>>>(q, w_g + i * ADIMD, a);
        anorm_kernel<<<NB, 256>>>(a, rn);
        gsum_kernel<<<NB, ADIMD>>>(q, a, rn, G);
        // k <- G * k (elementwise, broadcast over tokens)
        kscale_kernel<<<(MROWS * ADIMD) / 1024, 1024>>>(k, G);
        // att = (G*k)@Wp + bp + q
        sgemm128<3><<<gQK, 256>>>(MROWS, ADIMD, ADIMD, k, Wp_i, bp + i * ADIMD, q, att);
        // x += att@Wf + bf
        sgemm128<1><<<gDIM, 256>>>(MROWS, DIMD, ADIMD, att, Wf_i, bf + i * DIMD, nullptr, x);
        // h = LN2(x)
        ln_kernel<<<MROWS, 256>>>(x, ln2_g + i * DIMD, ln2_b + i * DIMD, h);
        // hid = gelu(h@W1 + b1)
        sgemm128<2><<<gHID, 256>>>(MROWS, HIDD, DIMD, h, W1_i, b1 + i * HIDD, nullptr, hid);
        // x += hid@W2 + b2
        sgemm128<1><<<gDIM, 256>>>(MROWS, DIMD, HIDD, hid, W2_i, b2 + i * DIMD, nullptr, x);
    }
}

// round 3
// speedup vs baseline: 3.1467x; 3.1467x over previous
#include <cuda_runtime.h>
#include <math.h>

// Problem constants
#define DIMD  1024
#define ADIMD 256
#define HIDD  4096
#define NTOK  4096
#define NB    4
#define MROWS (NB * NTOK)        // 16384
#define DEPTH 4
#define SCALE_A 0.25f            // 16^-0.5

// ---------------- scratch (device globals; no allocation allowed) ----------
__device__ float g_h  [(size_t)MROWS * DIMD];    // 64 MB
__device__ float g_q  [(size_t)MROWS * ADIMD];   // 16 MB
__device__ float g_k  [(size_t)MROWS * ADIMD];   // 16 MB
__device__ float g_att[(size_t)MROWS * ADIMD];   // 16 MB
__device__ float g_hid[(size_t)MROWS * HIDD];    // 256 MB
__device__ float g_a  [MROWS];
__device__ float g_rn [NB];
__device__ float g_G  [NB * ADIMD];
__device__ float g_Gp [NB * 32 * ADIMD];

// ---------------- helpers ----------------
__device__ __forceinline__ float warpSum(float v) {
#pragma unroll
    for (int o = 16; o > 0; o >>= 1) v += __shfl_xor_sync(0xFFFFFFFFu, v, o);
    return v;
}

__device__ __forceinline__ float to_tf32(float x) {
    unsigned r;
    asm("cvt.rna.tf32.f32 %0, %1;" : "=r"(r) : "f"(x));
    return __uint_as_float(r);
}

__device__ __forceinline__ void mma_tf32(float& c0, float& c1, float& c2, float& c3,
                                         float a0, float a1, float a2, float a3,
                                         float b0, float b1) {
    asm volatile(
        "mma.sync.aligned.m16n8k8.row.col.f32.tf32.tf32.f32 "
        "{%0,%1,%2,%3}, {%4,%5,%6,%7}, {%8,%9}, {%0,%1,%2,%3};"
        : "+f"(c0), "+f"(c1), "+f"(c2), "+f"(c3)
        : "r"(__float_as_uint(a0)), "r"(__float_as_uint(a1)),
          "r"(__float_as_uint(a2)), "r"(__float_as_uint(a3)),
          "r"(__float_as_uint(b0)), "r"(__float_as_uint(b1)));
}

// ---------------- LayerNorm: one row (1024) per block of 256 threads -------
__global__ void ln_kernel(const float* __restrict__ x,
                          const float* __restrict__ g,
                          const float* __restrict__ b,
                          float* __restrict__ out) {
    int row = blockIdx.x;
    const float* xr = x + (size_t)row * DIMD;
    float v[4];
    float s = 0.f, s2 = 0.f;
#pragma unroll
    for (int j = 0; j < 4; j++) {
        v[j] = xr[threadIdx.x + 256 * j];
        s += v[j];
        s2 += v[j] * v[j];
    }
    __shared__ float sh[2][8];
    s = warpSum(s); s2 = warpSum(s2);
    int w = threadIdx.x >> 5, l = threadIdx.x & 31;
    if (l == 0) { sh[0][w] = s; sh[1][w] = s2; }
    __syncthreads();
    if (w == 0) {
        float a = (l < 8) ? sh[0][l] : 0.f;
        float c = (l < 8) ? sh[1][l] : 0.f;
        a = warpSum(a); c = warpSum(c);
        if (l == 0) { sh[0][0] = a; sh[1][0] = c; }
    }
    __syncthreads();
    float mu  = sh[0][0] * (1.f / DIMD);
    float var = sh[1][0] * (1.f / DIMD) - mu * mu;
    float rs  = rsqrtf(var + 1e-6f);
    float* orow = out + (size_t)row * DIMD;
#pragma unroll
    for (int j = 0; j < 4; j++) {
        int c = threadIdx.x + 256 * j;
        orow[c] = (v[j] - mu) * rs * g[c] + b[c];
    }
}

// ---------------- tf32 tensor-core GEMM: 128x128 tile, BK=32 ---------------
// EPI: 0 = C = AB + bias
//      1 = C += AB + bias
//      2 = C = gelu(AB + bias)
//      3 = C = AB + bias + D
#define BK 32
template <int EPI>
__global__ __launch_bounds__(256, 2)
void tgemm(int M, int N, int K,
           const float* __restrict__ A,
           const float* __restrict__ B,
           const float* __restrict__ bias,
           const float* __restrict__ D,
           float* __restrict__ C) {
    // As: [128][36], Bs: [32][132]  (padded, conflict-free fragment loads)
    __shared__ float As[128][BK + 4];
    __shared__ float Bs[BK][128 + 4];

    const int bx = blockIdx.x;
    const int by = blockIdx.y;
    const int tid = threadIdx.x;
    const int lane = tid & 31;
    const int warp = tid >> 5;
    const int warpM = warp & 1;         // 2 warps over M (64 rows each)
    const int warpN = warp >> 1;        // 4 warps over N (32 cols each)
    const int grp = lane >> 2;          // 0..7
    const int tg  = lane & 3;           // 0..3

    const float* Ab = A + (size_t)by * 128 * K;
    const float* Bb = B + bx * 128;

    // global-load addressing
    const int a_r = tid >> 3;           // 0..31
    const int a_c = (tid & 7) * 4;      // 0,4,...,28
    const int b_r = tid >> 5;           // 0..7
    const int b_c = (tid & 31) * 4;     // 0,4,...,124

    float acc[4][4][4];
#pragma unroll
    for (int mi = 0; mi < 4; mi++)
#pragma unroll
        for (int ni = 0; ni < 4; ni++)
#pragma unroll
            for (int r = 0; r < 4; r++) acc[mi][ni][r] = 0.f;

    const int TITER = K / BK;
    float4 aR[4], bR[4];

    // prefetch tile 0
#pragma unroll
    for (int p = 0; p < 4; p++)
        aR[p] = *(const float4*)(Ab + (size_t)(a_r + p * 32) * K + a_c);
#pragma unroll
    for (int p = 0; p < 4; p++)
        bR[p] = *(const float4*)(Bb + (size_t)(b_r + p * 8) * N + b_c);

    for (int t = 0; t < TITER; t++) {
        __syncthreads();
        // store staged tile (convert to tf32 once here)
#pragma unroll
        for (int p = 0; p < 4; p++) {
            As[a_r + p * 32][a_c + 0] = to_tf32(aR[p].x);
            As[a_r + p * 32][a_c + 1] = to_tf32(aR[p].y);
            As[a_r + p * 32][a_c + 2] = to_tf32(aR[p].z);
            As[a_r + p * 32][a_c + 3] = to_tf32(aR[p].w);
            Bs[b_r + p * 8][b_c + 0] = to_tf32(bR[p].x);
            Bs[b_r + p * 8][b_c + 1] = to_tf32(bR[p].y);
            Bs[b_r + p * 8][b_c + 2] = to_tf32(bR[p].z);
            Bs[b_r + p * 8][b_c + 3] = to_tf32(bR[p].w);
        }
        __syncthreads();

        // issue next-tile loads (latency hidden behind the MMAs)
        if (t + 1 < TITER) {
            int k0 = (t + 1) * BK;
#pragma unroll
            for (int p = 0; p < 4; p++)
                aR[p] = *(const float4*)(Ab + (size_t)(a_r + p * 32) * K + k0 + a_c);
#pragma unroll
            for (int p = 0; p < 4; p++)
                bR[p] = *(const float4*)(Bb + (size_t)(k0 + b_r + p * 8) * N + b_c);
        }

#pragma unroll
        for (int ks = 0; ks < 4; ks++) {
            float af[4][4], bf[4][2];
#pragma unroll
            for (int mi = 0; mi < 4; mi++) {
                int rb = warpM * 64 + mi * 16;
                int kk = ks * 8 + tg;
                af[mi][0] = As[rb + grp][kk];
                af[mi][1] = As[rb + grp + 8][kk];
                af[mi][2] = As[rb + grp][kk + 4];
                af[mi][3] = As[rb + grp + 8][kk + 4];
            }
#pragma unroll
            for (int ni = 0; ni < 4; ni++) {
                int col = warpN * 32 + ni * 8 + grp;
                bf[ni][0] = Bs[ks * 8 + tg][col];
                bf[ni][1] = Bs[ks * 8 + tg + 4][col];
            }
#pragma unroll
            for (int mi = 0; mi < 4; mi++)
#pragma unroll
                for (int ni = 0; ni < 4; ni++)
                    mma_tf32(acc[mi][ni][0], acc[mi][ni][1],
                             acc[mi][ni][2], acc[mi][ni][3],
                             af[mi][0], af[mi][1], af[mi][2], af[mi][3],
                             bf[ni][0], bf[ni][1]);
        }
    }

    // epilogue: thread (mi,ni) owns rows {r, r+8}, cols {c, c+1}
#pragma unroll
    for (int mi = 0; mi < 4; mi++) {
#pragma unroll
        for (int ni = 0; ni < 4; ni++) {
            int col = bx * 128 + warpN * 32 + ni * 8 + 2 * tg;
            int row0 = by * 128 + warpM * 64 + mi * 16 + grp;
            float bv0 = bias[col], bv1 = bias[col + 1];
#pragma unroll
            for (int half = 0; half < 2; half++) {
                int row = row0 + half * 8;
                float v0 = acc[mi][ni][half * 2 + 0] + bv0;
                float v1 = acc[mi][ni][half * 2 + 1] + bv1;
                float* Cp = C + (size_t)row * N + col;
                if (EPI == 1) {
                    float2 old = *(const float2*)Cp;
                    v0 += old.x; v1 += old.y;
                }
                if (EPI == 2) {
                    v0 = 0.5f * v0 * (1.0f + erff(v0 * 0.70710678118654752f));
                    v1 = 0.5f * v1 * (1.0f + erff(v1 * 0.70710678118654752f));
                }
                if (EPI == 3) {
                    const float2 dv = *(const float2*)(D + (size_t)row * N + col);
                    v0 += dv.x; v1 += dv.y;
                }
                *(float2*)Cp = make_float2(v0, v1);
            }
        }
    }
}

// ---------------- L2-normalize each 256-wide row (one warp per row) --------
__global__ void rownorm_kernel(float* __restrict__ q) {
    int row  = blockIdx.x * 8 + (threadIdx.x >> 5);
    int lane = threadIdx.x & 31;
    float4* r = (float4*)(q + (size_t)row * ADIMD);
    float4 v0 = r[lane];
    float4 v1 = r[lane + 32];
    float s = v0.x * v0.x + v0.y * v0.y + v0.z * v0.z + v0.w * v0.w
            + v1.x * v1.x + v1.y * v1.y + v1.z * v1.z + v1.w * v1.w;
    s = warpSum(s);
    float inv = 1.0f / fmaxf(sqrtf(s), 1e-12f);
    v0.x *= inv; v0.y *= inv; v0.z *= inv; v0.w *= inv;
    v1.x *= inv; v1.y *= inv; v1.z *= inv; v1.w *= inv;
    r[lane]      = v0;
    r[lane + 32] = v1;
}

// ---------------- a[row] = SCALE * dot(q[row,:], wg) ----------------------
__global__ void adot_kernel(const float* __restrict__ q,
                            const float* __restrict__ wg,
                            float* __restrict__ a) {
    int row  = blockIdx.x * 8 + (threadIdx.x >> 5);
    int lane = threadIdx.x & 31;
    const float4* r = (const float4*)(q + (size_t)row * ADIMD);
    const float4* w = (const float4*)wg;
    float4 v0 = r[lane],     w0 = w[lane];
    float4 v1 = r[lane + 32], w1 = w[lane + 32];
    float s = v0.x * w0.x + v0.y * w0.y + v0.z * w0.z + v0.w * w0.w
            + v1.x * w1.x + v1.y * w1.y + v1.z * w1.z + v1.w * w1.w;
    s = warpSum(s);
    if (lane == 0) a[row] = s * SCALE_A;
}

// ---------------- per-batch 1/||a|| over 4096 tokens ----------------------
__global__ void anorm_kernel(const float* __restrict__ a, float* __restrict__ rn) {
    int b = blockIdx.x;
    float s = 0.f;
    for (int n = threadIdx.x; n < NTOK; n += 256) {
        float v = a[b * NTOK + n];
        s += v * v;
    }
    __shared__ float sh[8];
    s = warpSum(s);
    int w = threadIdx.x >> 5, l = threadIdx.x & 31;
    if (l == 0) sh[w] = s;
    __syncthreads();
    if (w == 0) {
        float v = (l < 8) ? sh[l] : 0.f;
        v = warpSum(v);
        if (l == 0) rn[b] = 1.0f / fmaxf(sqrtf(v), 1e-12f);
    }
}

// ---------------- G partials: block = (b, chunk of 128 tokens) -------------
__global__ void gsum1_kernel(const float* __restrict__ q,
                             const float* __restrict__ a,
                             float* __restrict__ Gp) {
    int b  = blockIdx.x >> 5;
    int ch = blockIdx.x & 31;
    int c  = threadIdx.x;
    const float* qb = q + ((size_t)b * NTOK + (size_t)ch * 128) * ADIMD;
    const float* ab = a + b * NTOK + ch * 128;
    float s = 0.f;
#pragma unroll 4
    for (int n = 0; n < 128; n++)
        s += ab[n] * qb[(size_t)n * ADIMD + c];
    Gp[(size_t)blockIdx.x * ADIMD + c] = s;
}

// ---------------- G reduce: G[b,c] = rn[b] * sum_ch Gp --------------------
__global__ void gsum2_kernel(const float* __restrict__ Gp,
                             const float* __restrict__ rn,
                             float* __restrict__ G) {
    int b = blockIdx.x;
    int c = threadIdx.x;
    float s = 0.f;
#pragma unroll
    for (int ch = 0; ch < 32; ch++)
        s += Gp[((size_t)b * 32 + ch) * ADIMD + c];
    G[b * ADIMD + c] = s * rn[b];
}

// ---------------- k[b,n,c] *= G[b,c] --------------------------------------
__global__ void kscale_kernel(float* __restrict__ k, const float* __restrict__ G) {
    int idx = blockIdx.x * 1024 + threadIdx.x;
    int b = idx >> 20;
    int c = idx & 255;
    k[idx] *= G[b * ADIMD + c];
}

// ---------------- host orchestration --------------------------------------
extern "C" void kernel_launch(void* const* d_in, const int* in_sizes, int n_in,
                              void* d_out, int out_size) {
    const float* x_in  = (const float*)d_in[0];
    const float* ln1_g = (const float*)d_in[1];
    const float* ln1_b = (const float*)d_in[2];
    const float* Wq    = (const float*)d_in[3];
    const float* bq    = (const float*)d_in[4];
    const float* Wk    = (const float*)d_in[5];
    const float* bk    = (const float*)d_in[6];
    const float* w_g   = (const float*)d_in[7];
    const float* Wp    = (const float*)d_in[8];
    const float* bp    = (const float*)d_in[9];
    const float* Wf    = (const float*)d_in[10];
    const float* bf    = (const float*)d_in[11];
    const float* ln2_g = (const float*)d_in[12];
    const float* ln2_b = (const float*)d_in[13];
    const float* W1    = (const float*)d_in[14];
    const float* b1    = (const float*)d_in[15];
    const float* W2    = (const float*)d_in[16];
    const float* b2    = (const float*)d_in[17];

    float* x = (float*)d_out;

    void* p;
    cudaGetSymbolAddress(&p, g_h);   float* h   = (float*)p;
    cudaGetSymbolAddress(&p, g_q);   float* q   = (float*)p;
    cudaGetSymbolAddress(&p, g_k);   float* k   = (float*)p;
    cudaGetSymbolAddress(&p, g_att); float* att = (float*)p;
    cudaGetSymbolAddress(&p, g_hid); float* hid = (float*)p;
    cudaGetSymbolAddress(&p, g_a);   float* a   = (float*)p;
    cudaGetSymbolAddress(&p, g_rn);  float* rn  = (float*)p;
    cudaGetSymbolAddress(&p, g_G);   float* G   = (float*)p;
    cudaGetSymbolAddress(&p, g_Gp);  float* Gp  = (float*)p;

    cudaMemcpyAsync(x, x_in, sizeof(float) * (size_t)MROWS * DIMD,
                    cudaMemcpyDeviceToDevice);

    const dim3 gQK (ADIMD / 128, MROWS / 128);
    const dim3 gDIM(DIMD  / 128, MROWS / 128);
    const dim3 gHID(HIDD  / 128, MROWS / 128);

    for (int i = 0; i < DEPTH; i++) {
        const float* Wq_i = Wq + (size_t)i * DIMD * ADIMD;
        const float* Wk_i = Wk + (size_t)i * DIMD * ADIMD;
        const float* Wp_i = Wp + (size_t)i * ADIMD * ADIMD;
        const float* Wf_i = Wf + (size_t)i * ADIMD * DIMD;
        const float* W1_i = W1 + (size_t)i * DIMD * HIDD;
        const float* W2_i = W2 + (size_t)i * HIDD * DIMD;

        ln_kernel<<<MROWS, 256>>>(x, ln1_g + i * DIMD, ln1_b + i * DIMD, h);
        tgemm<0><<<gQK, 256>>>(MROWS, ADIMD, DIMD, h, Wq_i, bq + i * ADIMD, nullptr, q);
        tgemm<0><<<gQK, 256>>>(MROWS, ADIMD, DIMD, h, Wk_i, bk + i * ADIMD, nullptr, k);
        rownorm_kernel<<<MROWS / 8, 256>>>(q);
        rownorm_kernel<<<MROWS / 8, 256>>>(k);
        adot_kernel<<<MROWS / 8, 256>>>(q, w_g + i * ADIMD, a);
        anorm_kernel<<<NB, 256>>>(a, rn);
        gsum1_kernel<<<NB * 32, ADIMD>>>(q, a, Gp);
        gsum2_kernel<<<NB, ADIMD>>>(Gp, rn, G);
        kscale_kernel<<<(MROWS * ADIMD) / 1024, 1024>>>(k, G);
        tgemm<3><<<gQK, 256>>>(MROWS, ADIMD, ADIMD, k, Wp_i, bp + i * ADIMD, q, att);
        tgemm<1><<<gDIM, 256>>>(MROWS, DIMD, ADIMD, att, Wf_i, bf + i * DIMD, nullptr, x);
        ln_kernel<<<MROWS, 256>>>(x, ln2_g + i * DIMD, ln2_b + i * DIMD, h);
        tgemm<2><<<gHID, 256>>>(MROWS, HIDD, DIMD, h, W1_i, b1 + i * HIDD, nullptr, hid);
        tgemm<1><<<gDIM, 256>>>(MROWS, DIMD, HIDD, hid, W2_i, b2 + i * DIMD, nullptr, x);
    }
}

// round 5
// speedup vs baseline: 5.0272x; 1.5976x over previous
#include <cuda_runtime.h>
#include <cuda_fp16.h>
#include <math.h>
#include <stdint.h>

#define DIMD  1024
#define ADIMD 256
#define HIDD  4096
#define NTOK  4096
#define NB    4
#define MROWS (NB * NTOK)        // 16384
#define DEPTH 4
#define SCALE_A 0.25f

// ---------------- scratch (device globals) ----------------
__device__ __half g_h  [(size_t)MROWS * DIMD];
__device__ __half g_q  [(size_t)MROWS * ADIMD];
__device__ __half g_k  [(size_t)MROWS * ADIMD];
__device__ __half g_att[(size_t)MROWS * ADIMD];
__device__ __half g_hid[(size_t)MROWS * HIDD];
__device__ float  g_a  [MROWS];
__device__ float  g_rn [NB];
__device__ float  g_G  [NB * ADIMD];
__device__ float  g_Gp [NB * 32 * ADIMD];
// transposed fp16 weights [N][K]
__device__ __half g_Wqt[(size_t)DEPTH * ADIMD * DIMD];
__device__ __half g_Wkt[(size_t)DEPTH * ADIMD * DIMD];
__device__ __half g_Wpt[(size_t)DEPTH * ADIMD * ADIMD];
__device__ __half g_Wft[(size_t)DEPTH * DIMD * ADIMD];
__device__ __half g_W1t[(size_t)DEPTH * HIDD * DIMD];
__device__ __half g_W2t[(size_t)DEPTH * DIMD * HIDD];

// ---------------- helpers ----------------
__device__ __forceinline__ float warpSum(float v) {
#pragma unroll
    for (int o = 16; o > 0; o >>= 1) v += __shfl_xor_sync(0xFFFFFFFFu, v, o);
    return v;
}

__device__ __forceinline__ void mma_f16(float& c0, float& c1, float& c2, float& c3,
                                        uint32_t a0, uint32_t a1, uint32_t a2, uint32_t a3,
                                        uint32_t b0, uint32_t b1) {
    asm volatile(
        "mma.sync.aligned.m16n8k16.row.col.f32.f16.f16.f32 "
        "{%0,%1,%2,%3}, {%4,%5,%6,%7}, {%8,%9}, {%0,%1,%2,%3};"
        : "+f"(c0), "+f"(c1), "+f"(c2), "+f"(c3)
        : "r"(a0), "r"(a1), "r"(a2), "r"(a3), "r"(b0), "r"(b1));
}

// ================= fp16 tensor-core GEMM: 128x128 tile, BK=32 ==============
// EPI: 0 = half(AB+bias) | 1 = Cf32 += AB+bias | 2 = half(gelu(AB+bias))
//      3 = half(AB+bias+D)
#define BKH 32
template <int EPI>
__global__ __launch_bounds__(256, 2)
void hgemm(int N, int K,
           const __half* __restrict__ A,     // [M][K]
           const __half* __restrict__ Bt,    // [N][K]
           const float* __restrict__ bias,   // [N]
           const __half* __restrict__ Dadd,  // [M][N] (EPI 3)
           void* __restrict__ Cv) {
    __shared__ __half As[128][40];   // 40-half stride: 80B rows (16B-aligned, conflict-free)
    __shared__ __half Bs[128][40];

    const int bx = blockIdx.x;          // N tile
    const int by = blockIdx.y;          // M tile
    const int tid = threadIdx.x;
    const int lane = tid & 31;
    const int warp = tid >> 5;
    const int warpM = warp & 1;         // 2 warps over M (64 rows)
    const int warpN = warp >> 1;        // 4 warps over N (32 cols)
    const int grp = lane >> 2;          // 0..7
    const int tg  = lane & 3;           // 0..3

    const __half* Ab = A  + (size_t)by * 128 * K;
    const __half* Bb = Bt + (size_t)bx * 128 * K;

    // global-load geometry: each thread moves 2 x 16B for A and 2 x 16B for B
    const int l_r = tid >> 2;           // 0..63 (and +64)
    const int l_c = (tid & 3) * 8;      // half offset 0,8,16,24

    float acc[4][4][4];
#pragma unroll
    for (int mi = 0; mi < 4; mi++)
#pragma unroll
        for (int ni = 0; ni < 4; ni++)
#pragma unroll
            for (int r = 0; r < 4; r++) acc[mi][ni][r] = 0.f;

    const int T = K / BKH;
    float4 aR[2], bR[2];

    aR[0] = *(const float4*)(Ab + (size_t)l_r * K + l_c);
    aR[1] = *(const float4*)(Ab + (size_t)(l_r + 64) * K + l_c);
    bR[0] = *(const float4*)(Bb + (size_t)l_r * K + l_c);
    bR[1] = *(const float4*)(Bb + (size_t)(l_r + 64) * K + l_c);

    for (int t = 0; t < T; t++) {
        __syncthreads();
        *(float4*)&As[l_r][l_c]      = aR[0];
        *(float4*)&As[l_r + 64][l_c] = aR[1];
        *(float4*)&Bs[l_r][l_c]      = bR[0];
        *(float4*)&Bs[l_r + 64][l_c] = bR[1];
        __syncthreads();

        if (t + 1 < T) {
            int k0 = (t + 1) * BKH;
            aR[0] = *(const float4*)(Ab + (size_t)l_r * K + k0 + l_c);
            aR[1] = *(const float4*)(Ab + (size_t)(l_r + 64) * K + k0 + l_c);
            bR[0] = *(const float4*)(Bb + (size_t)l_r * K + k0 + l_c);
            bR[1] = *(const float4*)(Bb + (size_t)(l_r + 64) * K + k0 + l_c);
        }

#pragma unroll
        for (int ks = 0; ks < 2; ks++) {
            const int kb = ks * 16;
            uint32_t af[4][4], bf[4][2];
#pragma unroll
            for (int mi = 0; mi < 4; mi++) {
                int rb = warpM * 64 + mi * 16;
                af[mi][0] = *(const uint32_t*)&As[rb + grp][kb + 2 * tg];
                af[mi][1] = *(const uint32_t*)&As[rb + grp + 8][kb + 2 * tg];
                af[mi][2] = *(const uint32_t*)&As[rb + grp][kb + 2 * tg + 8];
                af[mi][3] = *(const uint32_t*)&As[rb + grp + 8][kb + 2 * tg + 8];
            }
#pragma unroll
            for (int ni = 0; ni < 4; ni++) {
                int cb = warpN * 32 + ni * 8;
                bf[ni][0] = *(const uint32_t*)&Bs[cb + grp][kb + 2 * tg];
                bf[ni][1] = *(const uint32_t*)&Bs[cb + grp][kb + 2 * tg + 8];
            }
#pragma unroll
            for (int mi = 0; mi < 4; mi++)
#pragma unroll
                for (int ni = 0; ni < 4; ni++)
                    mma_f16(acc[mi][ni][0], acc[mi][ni][1],
                            acc[mi][ni][2], acc[mi][ni][3],
                            af[mi][0], af[mi][1], af[mi][2], af[mi][3],
                            bf[ni][0], bf[ni][1]);
        }
    }

    // epilogue: thread (mi,ni) owns rows {grp, grp+8}, cols {2tg, 2tg+1}
#pragma unroll
    for (int mi = 0; mi < 4; mi++) {
#pragma unroll
        for (int ni = 0; ni < 4; ni++) {
            int col = bx * 128 + warpN * 32 + ni * 8 + 2 * tg;
            int row0 = by * 128 + warpM * 64 + mi * 16 + grp;
            float bv0 = bias[col], bv1 = bias[col + 1];
#pragma unroll
            for (int hh = 0; hh < 2; hh++) {
                int row = row0 + hh * 8;
                float v0 = acc[mi][ni][hh * 2 + 0] + bv0;
                float v1 = acc[mi][ni][hh * 2 + 1] + bv1;
                if (EPI == 1) {
                    float* Cp = (float*)Cv + (size_t)row * N + col;
                    float2 old = *(const float2*)Cp;
                    *(float2*)Cp = make_float2(v0 + old.x, v1 + old.y);
                } else {
                    __half* Cp = (__half*)Cv + (size_t)row * N + col;
                    if (EPI == 2) {
                        v0 = 0.5f * v0 * (1.0f + erff(v0 * 0.70710678118654752f));
                        v1 = 0.5f * v1 * (1.0f + erff(v1 * 0.70710678118654752f));
                    }
                    if (EPI == 3) {
                        float2 dv = __half22float2(
                            *(const __half2*)(Dadd + (size_t)row * N + col));
                        v0 += dv.x; v1 += dv.y;
                    }
                    *(__half2*)Cp = __floats2half2_rn(v0, v1);
                }
            }
        }
    }
}

// ---------------- weight transpose to fp16: W[K][N] -> Wt[N][K] ------------
__global__ void transpose_half(const float* __restrict__ W, __half* __restrict__ Wt,
                               int K, int N) {
    __shared__ float t[32][33];
    int n0 = blockIdx.x * 32, k0 = blockIdx.y * 32;
    int tx = threadIdx.x, ty = threadIdx.y;     // 32 x 8
#pragma unroll
    for (int i = 0; i < 4; i++)
        t[ty + 8 * i][tx] = W[(size_t)(k0 + ty + 8 * i) * N + n0 + tx];
    __syncthreads();
#pragma unroll
    for (int i = 0; i < 4; i++)
        Wt[(size_t)(n0 + ty + 8 * i) * K + k0 + tx] = __float2half(t[tx][ty + 8 * i]);
}

// ---------------- LayerNorm (fp32 in, fp16 out) ---------------------------
__global__ void ln_kernel(const float* __restrict__ x,
                          const float* __restrict__ g,
                          const float* __restrict__ b,
                          __half* __restrict__ out) {
    int row = blockIdx.x;
    const float* xr = x + (size_t)row * DIMD;
    float v[4];
    float s = 0.f, s2 = 0.f;
#pragma unroll
    for (int j = 0; j < 4; j++) {
        v[j] = xr[threadIdx.x + 256 * j];
        s += v[j]; s2 += v[j] * v[j];
    }
    __shared__ float sh[2][8];
    s = warpSum(s); s2 = warpSum(s2);
    int w = threadIdx.x >> 5, l = threadIdx.x & 31;
    if (l == 0) { sh[0][w] = s; sh[1][w] = s2; }
    __syncthreads();
    if (w == 0) {
        float a = (l < 8) ? sh[0][l] : 0.f;
        float c = (l < 8) ? sh[1][l] : 0.f;
        a = warpSum(a); c = warpSum(c);
        if (l == 0) { sh[0][0] = a; sh[1][0] = c; }
    }
    __syncthreads();
    float mu  = sh[0][0] * (1.f / DIMD);
    float var = sh[1][0] * (1.f / DIMD) - mu * mu;
    float rs  = rsqrtf(var + 1e-6f);
    __half* orow = out + (size_t)row * DIMD;
#pragma unroll
    for (int j = 0; j < 4; j++) {
        int c = threadIdx.x + 256 * j;
        orow[c] = __float2half((v[j] - mu) * rs * g[c] + b[c]);
    }
}

// ---------------- L2-normalize each 256-wide fp16 row (warp/row) ----------
__global__ void rownorm_kernel(__half* __restrict__ q) {
    int row  = blockIdx.x * 8 + (threadIdx.x >> 5);
    int lane = threadIdx.x & 31;
    float4* r = (float4*)(q + (size_t)row * ADIMD);    // 32 x float4 = 256 halfs
    float4 v = r[lane];
    __half2* h2 = (__half2*)&v;
    float s = 0.f;
    float2 f[4];
#pragma unroll
    for (int i = 0; i < 4; i++) {
        f[i] = __half22float2(h2[i]);
        s += f[i].x * f[i].x + f[i].y * f[i].y;
    }
    s = warpSum(s);
    float inv = 1.0f / fmaxf(sqrtf(s), 1e-12f);
#pragma unroll
    for (int i = 0; i < 4; i++)
        h2[i] = __floats2half2_rn(f[i].x * inv, f[i].y * inv);
    r[lane] = v;
}

// ---------------- a[row] = SCALE * dot(q[row,:], wg) ----------------------
__global__ void adot_kernel(const __half* __restrict__ q,
                            const float* __restrict__ wg,
                            float* __restrict__ a) {
    int row  = blockIdx.x * 8 + (threadIdx.x >> 5);
    int lane = threadIdx.x & 31;
    const float4* r = (const float4*)(q + (size_t)row * ADIMD);
    float4 v = r[lane];
    const __half2* h2 = (const __half2*)&v;
    const float4* w4 = (const float4*)wg;
    float4 w0 = w4[lane * 2], w1 = w4[lane * 2 + 1];
    float2 f0 = __half22float2(h2[0]), f1 = __half22float2(h2[1]);
    float2 f2 = __half22float2(h2[2]), f3 = __half22float2(h2[3]);
    float s = f0.x * w0.x + f0.y * w0.y + f1.x * w0.z + f1.y * w0.w
            + f2.x * w1.x + f2.y * w1.y + f3.x * w1.z + f3.y * w1.w;
    s = warpSum(s);
    if (lane == 0) a[row] = s * SCALE_A;
}

__global__ void anorm_kernel(const float* __restrict__ a, float* __restrict__ rn) {
    int b = blockIdx.x;
    float s = 0.f;
    for (int n = threadIdx.x; n < NTOK; n += 256) {
        float v = a[b * NTOK + n];
        s += v * v;
    }
    __shared__ float sh[8];
    s = warpSum(s);
    int w = threadIdx.x >> 5, l = threadIdx.x & 31;
    if (l == 0) sh[w] = s;
    __syncthreads();
    if (w == 0) {
        float v = (l < 8) ? sh[l] : 0.f;
        v = warpSum(v);
        if (l == 0) rn[b] = 1.0f / fmaxf(sqrtf(v), 1e-12f);
    }
}

__global__ void gsum1_kernel(const __half* __restrict__ q,
                             const float* __restrict__ a,
                             float* __restrict__ Gp) {
    int b  = blockIdx.x >> 5;
    int ch = blockIdx.x & 31;
    int c  = threadIdx.x;
    const __half* qb = q + ((size_t)b * NTOK + (size_t)ch * 128) * ADIMD;
    const float* ab = a + b * NTOK + ch * 128;
    float s = 0.f;
#pragma unroll 4
    for (int n = 0; n < 128; n++)
        s += ab[n] * __half2float(qb[(size_t)n * ADIMD + c]);
    Gp[(size_t)blockIdx.x * ADIMD + c] = s;
}

__global__ void gsum2_kernel(const float* __restrict__ Gp,
                             const float* __restrict__ rn,
                             float* __restrict__ G) {
    int b = blockIdx.x;
    int c = threadIdx.x;
    float s = 0.f;
#pragma unroll
    for (int ch = 0; ch < 32; ch++)
        s += Gp[((size_t)b * 32 + ch) * ADIMD + c];
    G[b * ADIMD + c] = s * rn[b];
}

__global__ void kscale_kernel(__half* __restrict__ k, const float* __restrict__ G) {
    int idx = blockIdx.x * 1024 + threadIdx.x;      // over half2 pairs: 2M
    int e = idx * 2;
    int b = e >> 20;
    int c = e & 255;
    __half2* kp = (__half2*)k + idx;
    float2 f = __half22float2(*kp);
    *kp = __floats2half2_rn(f.x * G[b * ADIMD + c], f.y * G[b * ADIMD + c + 1]);
}

// ---------------- host orchestration --------------------------------------
extern "C" void kernel_launch(void* const* d_in, const int* in_sizes, int n_in,
                              void* d_out, int out_size) {
    const float* x_in  = (const float*)d_in[0];
    const float* ln1_g = (const float*)d_in[1];
    const float* ln1_b = (const float*)d_in[2];
    const float* Wq    = (const float*)d_in[3];
    const float* bq    = (const float*)d_in[4];
    const float* Wk    = (const float*)d_in[5];
    const float* bk    = (const float*)d_in[6];
    const float* w_g   = (const float*)d_in[7];
    const float* Wp    = (const float*)d_in[8];
    const float* bp    = (const float*)d_in[9];
    const float* Wf    = (const float*)d_in[10];
    const float* bf    = (const float*)d_in[11];
    const float* ln2_g = (const float*)d_in[12];
    const float* ln2_b = (const float*)d_in[13];
    const float* W1    = (const float*)d_in[14];
    const float* b1    = (const float*)d_in[15];
    const float* W2    = (const float*)d_in[16];
    const float* b2    = (const float*)d_in[17];

    float* x = (float*)d_out;

    void* p;
    cudaGetSymbolAddress(&p, g_h);   __half* h   = (__half*)p;
    cudaGetSymbolAddress(&p, g_q);   __half* q   = (__half*)p;
    cudaGetSymbolAddress(&p, g_k);   __half* k   = (__half*)p;
    cudaGetSymbolAddress(&p, g_att); __half* att = (__half*)p;
    cudaGetSymbolAddress(&p, g_hid); __half* hid = (__half*)p;
    cudaGetSymbolAddress(&p, g_a);   float* a    = (float*)p;
    cudaGetSymbolAddress(&p, g_rn);  float* rn   = (float*)p;
    cudaGetSymbolAddress(&p, g_G);   float* G    = (float*)p;
    cudaGetSymbolAddress(&p, g_Gp);  float* Gp   = (float*)p;
    cudaGetSymbolAddress(&p, g_Wqt); __half* Wqt = (__half*)p;
    cudaGetSymbolAddress(&p, g_Wkt); __half* Wkt = (__half*)p;
    cudaGetSymbolAddress(&p, g_Wpt); __half* Wpt = (__half*)p;
    cudaGetSymbolAddress(&p, g_Wft); __half* Wft = (__half*)p;
    cudaGetSymbolAddress(&p, g_W1t); __half* W1t = (__half*)p;
    cudaGetSymbolAddress(&p, g_W2t); __half* W2t = (__half*)p;

    cudaMemcpyAsync(x, x_in, sizeof(float) * (size_t)MROWS * DIMD,
                    cudaMemcpyDeviceToDevice);

    dim3 tb(32, 8);
    for (int i = 0; i < DEPTH; i++) {
        transpose_half<<<dim3(ADIMD/32, DIMD/32), tb>>>(Wq + (size_t)i*DIMD*ADIMD, Wqt + (size_t)i*ADIMD*DIMD, DIMD, ADIMD);
        transpose_half<<<dim3(ADIMD/32, DIMD/32), tb>>>(Wk + (size_t)i*DIMD*ADIMD, Wkt + (size_t)i*ADIMD*DIMD, DIMD, ADIMD);
        transpose_half<<<dim3(ADIMD/32, ADIMD/32), tb>>>(Wp + (size_t)i*ADIMD*ADIMD, Wpt + (size_t)i*ADIMD*ADIMD, ADIMD, ADIMD);
        transpose_half<<<dim3(DIMD/32, ADIMD/32), tb>>>(Wf + (size_t)i*ADIMD*DIMD, Wft + (size_t)i*DIMD*ADIMD, ADIMD, DIMD);
        transpose_half<<<dim3(HIDD/32, DIMD/32), tb>>>(W1 + (size_t)i*DIMD*HIDD, W1t + (size_t)i*HIDD*DIMD, DIMD, HIDD);
        transpose_half<<<dim3(DIMD/32, HIDD/32), tb>>>(W2 + (size_t)i*HIDD*DIMD, W2t + (size_t)i*DIMD*HIDD, HIDD, DIMD);
    }

    const dim3 gQK (ADIMD / 128, MROWS / 128);
    const dim3 gDIM(DIMD  / 128, MROWS / 128);
    const dim3 gHID(HIDD  / 128, MROWS / 128);

    for (int i = 0; i < DEPTH; i++) {
        const __half* Wqt_i = Wqt + (size_t)i * ADIMD * DIMD;
        const __half* Wkt_i = Wkt + (size_t)i * ADIMD * DIMD;
        const __half* Wpt_i = Wpt + (size_t)i * ADIMD * ADIMD;
        const __half* Wft_i = Wft + (size_t)i * DIMD * ADIMD;
        const __half* W1t_i = W1t + (size_t)i * HIDD * DIMD;
        const __half* W2t_i = W2t + (size_t)i * DIMD * HIDD;

        ln_kernel<<<MROWS, 256>>>(x, ln1_g + i * DIMD, ln1_b + i * DIMD, h);
        hgemm<0><<<gQK, 256>>>(ADIMD, DIMD, h, Wqt_i, bq + i * ADIMD, nullptr, q);
        hgemm<0><<<gQK, 256>>>(ADIMD, DIMD, h, Wkt_i, bk + i * ADIMD, nullptr, k);
        rownorm_kernel<<<MROWS / 8, 256>>>(q);
        rownorm_kernel<<<MROWS / 8, 256>>>(k);
        adot_kernel<<<MROWS / 8, 256>>>(q, w_g + i * ADIMD, a);
        anorm_kernel<<<NB, 256>>>(a, rn);
        gsum1_kernel<<<NB * 32, ADIMD>>>(q, a, Gp);
        gsum2_kernel<<<NB, ADIMD>>>(Gp, rn, G);
        kscale_kernel<<<(MROWS * ADIMD / 2) / 1024, 1024>>>(k, G);
        hgemm<3><<<gQK, 256>>>(ADIMD, ADIMD, k, Wpt_i, bp + i * ADIMD, q, att);
        hgemm<1><<<gDIM, 256>>>(DIMD, ADIMD, att, Wft_i, bf + i * DIMD, nullptr, x);
        ln_kernel<<<MROWS, 256>>>(x, ln2_g + i * DIMD, ln2_b + i * DIMD, h);
        hgemm<2><<<gHID, 256>>>(HIDD, DIMD, h, W1t_i, b1 + i * HIDD, nullptr, hid);
        hgemm<1><<<gDIM, 256>>>(DIMD, HIDD, hid, W2t_i, b2 + i * DIMD, nullptr, x);
    }
}

// round 6
// speedup vs baseline: 6.1449x; 1.2223x over previous
#include <cuda_runtime.h>
#include <cuda_fp16.h>
#include <math.h>
#include <stdint.h>

#define DIMD  1024
#define ADIMD 256
#define HIDD  4096
#define NTOK  4096
#define NB    4
#define MROWS (NB * NTOK)        // 16384
#define DEPTH 4
#define SCALE_A 0.25f

// ---------------- scratch (device globals) ----------------
__device__ __half g_h  [(size_t)MROWS * DIMD];
__device__ __half g_q  [(size_t)MROWS * ADIMD];
__device__ __half g_k  [(size_t)MROWS * ADIMD];
__device__ __half g_att[(size_t)MROWS * ADIMD];
__device__ __half g_hid[(size_t)MROWS * HIDD];
__device__ float  g_a  [MROWS];
__device__ float  g_rn [NB];
__device__ float  g_G  [NB * ADIMD];
__device__ float  g_Gp [NB * 32 * ADIMD];
__device__ __half g_Wqt[(size_t)DEPTH * ADIMD * DIMD];
__device__ __half g_Wkt[(size_t)DEPTH * ADIMD * DIMD];
__device__ __half g_Wpt[(size_t)DEPTH * ADIMD * ADIMD];
__device__ __half g_Wft[(size_t)DEPTH * DIMD * ADIMD];
__device__ __half g_W1t[(size_t)DEPTH * HIDD * DIMD];
__device__ __half g_W2t[(size_t)DEPTH * DIMD * HIDD];

// ---------------- helpers ----------------
__device__ __forceinline__ float warpSum(float v) {
#pragma unroll
    for (int o = 16; o > 0; o >>= 1) v += __shfl_xor_sync(0xFFFFFFFFu, v, o);
    return v;
}
__device__ __forceinline__ uint32_t smem_u32(const void* p) {
    uint32_t a;
    asm("{ .reg .u64 t; cvta.to.shared.u64 t, %1; cvt.u32.u64 %0, t; }" : "=r"(a) : "l"(p));
    return a;
}
__device__ __forceinline__ void cp_async16(uint32_t saddr, const void* g) {
    asm volatile("cp.async.cg.shared.global [%0], [%1], 16;" :: "r"(saddr), "l"(g));
}
__device__ __forceinline__ void cp_commit() { asm volatile("cp.async.commit_group;"); }
template <int N> __device__ __forceinline__ void cp_wait() {
    asm volatile("cp.async.wait_group %0;" :: "n"(N));
}
__device__ __forceinline__ void ldsm4(uint32_t& r0, uint32_t& r1, uint32_t& r2, uint32_t& r3,
                                      uint32_t addr) {
    asm volatile("ldmatrix.sync.aligned.m8n8.x4.shared.b16 {%0,%1,%2,%3}, [%4];"
                 : "=r"(r0), "=r"(r1), "=r"(r2), "=r"(r3) : "r"(addr));
}
__device__ __forceinline__ void mma_f16(float& c0, float& c1, float& c2, float& c3,
                                        uint32_t a0, uint32_t a1, uint32_t a2, uint32_t a3,
                                        uint32_t b0, uint32_t b1) {
    asm volatile(
        "mma.sync.aligned.m16n8k16.row.col.f32.f16.f16.f32 "
        "{%0,%1,%2,%3}, {%4,%5,%6,%7}, {%8,%9}, {%0,%1,%2,%3};"
        : "+f"(c0), "+f"(c1), "+f"(c2), "+f"(c3)
        : "r"(a0), "r"(a1), "r"(a2), "r"(a3), "r"(b0), "r"(b1));
}

// ================= fp16 pipelined GEMM: 128x128 tile, BK=32, 3 stages ======
// smem per stage: A 128 rows x 40 halfs (80B) = 10240B, B same.
#define A_BYTES     10240
#define STAGE_BYTES 20480
#define NSTAGE      3
#define SMEM_HGEMM  (NSTAGE * STAGE_BYTES)

// EPI: 0 = half(AB+bias) | 1 = Cf32 += AB+bias | 2 = half(gelu(AB+bias))
//      3 = half(AB+bias+D)
template <int EPI>
__global__ __launch_bounds__(256, 2)
void hgemm(int N, int K,
           const __half* __restrict__ A,     // [M][K]
           const __half* __restrict__ Bt,    // [N][K]
           const float* __restrict__ bias,   // [N]
           const __half* __restrict__ Dadd,  // [M][N] (EPI 3)
           void* __restrict__ Cv) {
    extern __shared__ char smraw[];
    const uint32_t sbase = smem_u32(smraw);

    const int bx = blockIdx.x, by = blockIdx.y;
    const int tid = threadIdx.x;
    const int lane = tid & 31;
    const int warp = tid >> 5;
    const int warpM = warp & 1;         // 2 warps over M (64 rows)
    const int warpN = warp >> 1;        // 4 warps over N (32 cols)
    const int grp = lane >> 3;          // unused for frag math, kept minimal
    (void)grp;
    const int tg  = lane & 3;

    const __half* Ab = A  + (size_t)by * 128 * K;
    const __half* Bb = Bt + (size_t)bx * 128 * K;

    // ldmatrix per-lane address components
    // A: addr = stage + (warpM*64 + (lane&15))*80 + (lane>>4)*16  [+ mi*1280 + ks*32]
    const uint32_t a_lane = (uint32_t)((warpM * 64 + (lane & 15)) * 80 + (lane >> 4) * 16);
    // B: addr = stage + A_BYTES + (warpN*32 + (lane&7) + 8*(lane>>4))*80
    //           + ((lane>>3)&1)*16                        [+ p*16*80 + ks*32]
    const uint32_t b_lane = (uint32_t)(A_BYTES +
        (warpN * 32 + (lane & 7) + 8 * (lane >> 4)) * 80 + ((lane >> 3) & 1) * 16);

    float acc[4][4][4];
#pragma unroll
    for (int mi = 0; mi < 4; mi++)
#pragma unroll
        for (int ni = 0; ni < 4; ni++)
#pragma unroll
            for (int r = 0; r < 4; r++) acc[mi][ni][r] = 0.f;

    const int T = K / 32;

    // global-load geometry: 512 16B-chunks per matrix per tile; 2 per thread
#define LOAD_TILE(t_, s_) do {                                                \
        uint32_t _sa = sbase + (s_) * STAGE_BYTES;                            \
        uint32_t _sb = _sa + A_BYTES;                                         \
        const __half* _ga = Ab + (size_t)(t_) * 32;                          \
        const __half* _gb = Bb + (size_t)(t_) * 32;                          \
        _Pragma("unroll")                                                     \
        for (int _i = 0; _i < 2; _i++) {                                      \
            int _id = tid + _i * 256;                                         \
            int _r = _id >> 2, _c = _id & 3;                                  \
            cp_async16(_sa + _r * 80 + _c * 16, _ga + (size_t)_r * K + _c * 8); \
            cp_async16(_sb + _r * 80 + _c * 16, _gb + (size_t)_r * K + _c * 8); \
        }                                                                     \
        cp_commit();                                                          \
    } while (0)

    LOAD_TILE(0, 0);
    if (T > 1) LOAD_TILE(1, 1);
    else cp_commit();

    for (int t = 0; t < T; t++) {
        cp_wait<1>();
        __syncthreads();
        if (t + 2 < T) LOAD_TILE(t + 2, (t + 2) % NSTAGE);
        else cp_commit();

        const uint32_t st = sbase + (t % NSTAGE) * STAGE_BYTES;
        const uint32_t a0addr = st + a_lane;
        const uint32_t b0addr = st + b_lane;
#pragma unroll
        for (int ks = 0; ks < 2; ks++) {
            uint32_t af[4][4], bfr[4][2];
#pragma unroll
            for (int mi = 0; mi < 4; mi++)
                ldsm4(af[mi][0], af[mi][1], af[mi][2], af[mi][3],
                      a0addr + mi * 1280 + ks * 32);
#pragma unroll
            for (int p = 0; p < 2; p++)
                ldsm4(bfr[2 * p][0], bfr[2 * p][1], bfr[2 * p + 1][0], bfr[2 * p + 1][1],
                      b0addr + p * 1280 + ks * 32);
#pragma unroll
            for (int mi = 0; mi < 4; mi++)
#pragma unroll
                for (int ni = 0; ni < 4; ni++)
                    mma_f16(acc[mi][ni][0], acc[mi][ni][1],
                            acc[mi][ni][2], acc[mi][ni][3],
                            af[mi][0], af[mi][1], af[mi][2], af[mi][3],
                            bfr[ni][0], bfr[ni][1]);
        }
        __syncthreads();
    }

    // epilogue: thread owns rows {grp8, grp8+8} x cols {2tg, 2tg+1} per (mi,ni)
    const int grp8 = lane >> 2;
#pragma unroll
    for (int mi = 0; mi < 4; mi++) {
#pragma unroll
        for (int ni = 0; ni < 4; ni++) {
            int col = bx * 128 + warpN * 32 + ni * 8 + 2 * tg;
            int row0 = by * 128 + warpM * 64 + mi * 16 + grp8;
            float bv0 = bias[col], bv1 = bias[col + 1];
#pragma unroll
            for (int hh = 0; hh < 2; hh++) {
                int row = row0 + hh * 8;
                float v0 = acc[mi][ni][hh * 2 + 0] + bv0;
                float v1 = acc[mi][ni][hh * 2 + 1] + bv1;
                if (EPI == 1) {
                    float* Cp = (float*)Cv + (size_t)row * N + col;
                    float2 old = *(const float2*)Cp;
                    *(float2*)Cp = make_float2(v0 + old.x, v1 + old.y);
                } else {
                    __half* Cp = (__half*)Cv + (size_t)row * N + col;
                    if (EPI == 2) {
                        v0 = 0.5f * v0 * (1.0f + erff(v0 * 0.70710678118654752f));
                        v1 = 0.5f * v1 * (1.0f + erff(v1 * 0.70710678118654752f));
                    }
                    if (EPI == 3) {
                        float2 dv = __half22float2(
                            *(const __half2*)(Dadd + (size_t)row * N + col));
                        v0 += dv.x; v1 += dv.y;
                    }
                    *(__half2*)Cp = __floats2half2_rn(v0, v1);
                }
            }
        }
    }
}

// ---------------- weight transpose to fp16: W[K][N] -> Wt[N][K] ------------
__global__ void transpose_half(const float* __restrict__ W, __half* __restrict__ Wt,
                               int K, int N) {
    __shared__ float t[32][33];
    int n0 = blockIdx.x * 32, k0 = blockIdx.y * 32;
    int tx = threadIdx.x, ty = threadIdx.y;     // 32 x 8
#pragma unroll
    for (int i = 0; i < 4; i++)
        t[ty + 8 * i][tx] = W[(size_t)(k0 + ty + 8 * i) * N + n0 + tx];
    __syncthreads();
#pragma unroll
    for (int i = 0; i < 4; i++)
        Wt[(size_t)(n0 + ty + 8 * i) * K + k0 + tx] = __float2half(t[tx][ty + 8 * i]);
}

// ---------------- LayerNorm (fp32 in, fp16 out) ---------------------------
__global__ void ln_kernel(const float* __restrict__ x,
                          const float* __restrict__ g,
                          const float* __restrict__ b,
                          __half* __restrict__ out) {
    int row = blockIdx.x;
    const float* xr = x + (size_t)row * DIMD;
    float v[4];
    float s = 0.f, s2 = 0.f;
#pragma unroll
    for (int j = 0; j < 4; j++) {
        v[j] = xr[threadIdx.x + 256 * j];
        s += v[j]; s2 += v[j] * v[j];
    }
    __shared__ float sh[2][8];
    s = warpSum(s); s2 = warpSum(s2);
    int w = threadIdx.x >> 5, l = threadIdx.x & 31;
    if (l == 0) { sh[0][w] = s; sh[1][w] = s2; }
    __syncthreads();
    if (w == 0) {
        float a = (l < 8) ? sh[0][l] : 0.f;
        float c = (l < 8) ? sh[1][l] : 0.f;
        a = warpSum(a); c = warpSum(c);
        if (l == 0) { sh[0][0] = a; sh[1][0] = c; }
    }
    __syncthreads();
    float mu  = sh[0][0] * (1.f / DIMD);
    float var = sh[1][0] * (1.f / DIMD) - mu * mu;
    float rs  = rsqrtf(var + 1e-6f);
    __half* orow = out + (size_t)row * DIMD;
#pragma unroll
    for (int j = 0; j < 4; j++) {
        int c = threadIdx.x + 256 * j;
        orow[c] = __float2half((v[j] - mu) * rs * g[c] + b[c]);
    }
}

// ---------------- L2-normalize each 256-wide fp16 row (warp/row) ----------
__global__ void rownorm_kernel(__half* __restrict__ q) {
    int row  = blockIdx.x * 8 + (threadIdx.x >> 5);
    int lane = threadIdx.x & 31;
    float4* r = (float4*)(q + (size_t)row * ADIMD);
    float4 v = r[lane];
    __half2* h2 = (__half2*)&v;
    float s = 0.f;
    float2 f[4];
#pragma unroll
    for (int i = 0; i < 4; i++) {
        f[i] = __half22float2(h2[i]);
        s += f[i].x * f[i].x + f[i].y * f[i].y;
    }
    s = warpSum(s);
    float inv = 1.0f / fmaxf(sqrtf(s), 1e-12f);
#pragma unroll
    for (int i = 0; i < 4; i++)
        h2[i] = __floats2half2_rn(f[i].x * inv, f[i].y * inv);
    r[lane] = v;
}

__global__ void adot_kernel(const __half* __restrict__ q,
                            const float* __restrict__ wg,
                            float* __restrict__ a) {
    int row  = blockIdx.x * 8 + (threadIdx.x >> 5);
    int lane = threadIdx.x & 31;
    const float4* r = (const float4*)(q + (size_t)row * ADIMD);
    float4 v = r[lane];
    const __half2* h2 = (const __half2*)&v;
    const float4* w4 = (const float4*)wg;
    float4 w0 = w4[lane * 2], w1 = w4[lane * 2 + 1];
    float2 f0 = __half22float2(h2[0]), f1 = __half22float2(h2[1]);
    float2 f2 = __half22float2(h2[2]), f3 = __half22float2(h2[3]);
    float s = f0.x * w0.x + f0.y * w0.y + f1.x * w0.z + f1.y * w0.w
            + f2.x * w1.x + f2.y * w1.y + f3.x * w1.z + f3.y * w1.w;
    s = warpSum(s);
    if (lane == 0) a[row] = s * SCALE_A;
}

__global__ void anorm_kernel(const float* __restrict__ a, float* __restrict__ rn) {
    int b = blockIdx.x;
    float s = 0.f;
    for (int n = threadIdx.x; n < NTOK; n += 256) {
        float v = a[b * NTOK + n];
        s += v * v;
    }
    __shared__ float sh[8];
    s = warpSum(s);
    int w = threadIdx.x >> 5, l = threadIdx.x & 31;
    if (l == 0) sh[w] = s;
    __syncthreads();
    if (w == 0) {
        float v = (l < 8) ? sh[l] : 0.f;
        v = warpSum(v);
        if (l == 0) rn[b] = 1.0f / fmaxf(sqrtf(v), 1e-12f);
    }
}

__global__ void gsum1_kernel(const __half* __restrict__ q,
                             const float* __restrict__ a,
                             float* __restrict__ Gp) {
    int b  = blockIdx.x >> 5;
    int ch = blockIdx.x & 31;
    int c  = threadIdx.x;
    const __half* qb = q + ((size_t)b * NTOK + (size_t)ch * 128) * ADIMD;
    const float* ab = a + b * NTOK + ch * 128;
    float s = 0.f;
#pragma unroll 4
    for (int n = 0; n < 128; n++)
        s += ab[n] * __half2float(qb[(size_t)n * ADIMD + c]);
    Gp[(size_t)blockIdx.x * ADIMD + c] = s;
}

__global__ void gsum2_kernel(const float* __restrict__ Gp,
                             const float* __restrict__ rn,
                             float* __restrict__ G) {
    int b = blockIdx.x;
    int c = threadIdx.x;
    float s = 0.f;
#pragma unroll
    for (int ch = 0; ch < 32; ch++)
        s += Gp[((size_t)b * 32 + ch) * ADIMD + c];
    G[b * ADIMD + c] = s * rn[b];
}

__global__ void kscale_kernel(__half* __restrict__ k, const float* __restrict__ G) {
    int idx = blockIdx.x * 1024 + threadIdx.x;      // over half2 pairs
    int e = idx * 2;
    int b = e >> 20;
    int c = e & 255;
    __half2* kp = (__half2*)k + idx;
    float2 f = __half22float2(*kp);
    *kp = __floats2half2_rn(f.x * G[b * ADIMD + c], f.y * G[b * ADIMD + c + 1]);
}

// ---------------- host orchestration --------------------------------------
extern "C" void kernel_launch(void* const* d_in, const int* in_sizes, int n_in,
                              void* d_out, int out_size) {
    const float* x_in  = (const float*)d_in[0];
    const float* ln1_g = (const float*)d_in[1];
    const float* ln1_b = (const float*)d_in[2];
    const float* Wq    = (const float*)d_in[3];
    const float* bq    = (const float*)d_in[4];
    const float* Wk    = (const float*)d_in[5];
    const float* bk    = (const float*)d_in[6];
    const float* w_g   = (const float*)d_in[7];
    const float* Wp    = (const float*)d_in[8];
    const float* bp    = (const float*)d_in[9];
    const float* Wf    = (const float*)d_in[10];
    const float* bf    = (const float*)d_in[11];
    const float* ln2_g = (const float*)d_in[12];
    const float* ln2_b = (const float*)d_in[13];
    const float* W1    = (const float*)d_in[14];
    const float* b1    = (const float*)d_in[15];
    const float* W2    = (const float*)d_in[16];
    const float* b2    = (const float*)d_in[17];

    float* x = (float*)d_out;

    void* p;
    cudaGetSymbolAddress(&p, g_h);   __half* h   = (__half*)p;
    cudaGetSymbolAddress(&p, g_q);   __half* q   = (__half*)p;
    cudaGetSymbolAddress(&p, g_k);   __half* k   = (__half*)p;
    cudaGetSymbolAddress(&p, g_att); __half* att = (__half*)p;
    cudaGetSymbolAddress(&p, g_hid); __half* hid = (__half*)p;
    cudaGetSymbolAddress(&p, g_a);   float* a    = (float*)p;
    cudaGetSymbolAddress(&p, g_rn);  float* rn   = (float*)p;
    cudaGetSymbolAddress(&p, g_G);   float* G    = (float*)p;
    cudaGetSymbolAddress(&p, g_Gp);  float* Gp   = (float*)p;
    cudaGetSymbolAddress(&p, g_Wqt); __half* Wqt = (__half*)p;
    cudaGetSymbolAddress(&p, g_Wkt); __half* Wkt = (__half*)p;
    cudaGetSymbolAddress(&p, g_Wpt); __half* Wpt = (__half*)p;
    cudaGetSymbolAddress(&p, g_Wft); __half* Wft = (__half*)p;
    cudaGetSymbolAddress(&p, g_W1t); __half* W1t = (__half*)p;
    cudaGetSymbolAddress(&p, g_W2t); __half* W2t = (__half*)p;

    cudaFuncSetAttribute(hgemm<0>, cudaFuncAttributeMaxDynamicSharedMemorySize, SMEM_HGEMM);
    cudaFuncSetAttribute(hgemm<1>, cudaFuncAttributeMaxDynamicSharedMemorySize, SMEM_HGEMM);
    cudaFuncSetAttribute(hgemm<2>, cudaFuncAttributeMaxDynamicSharedMemorySize, SMEM_HGEMM);
    cudaFuncSetAttribute(hgemm<3>, cudaFuncAttributeMaxDynamicSharedMemorySize, SMEM_HGEMM);

    cudaMemcpyAsync(x, x_in, sizeof(float) * (size_t)MROWS * DIMD,
                    cudaMemcpyDeviceToDevice);

    dim3 tb(32, 8);
    for (int i = 0; i < DEPTH; i++) {
        transpose_half<<<dim3(ADIMD/32, DIMD/32), tb>>>(Wq + (size_t)i*DIMD*ADIMD, Wqt + (size_t)i*ADIMD*DIMD, DIMD, ADIMD);
        transpose_half<<<dim3(ADIMD/32, DIMD/32), tb>>>(Wk + (size_t)i*DIMD*ADIMD, Wkt + (size_t)i*ADIMD*DIMD, DIMD, ADIMD);
        transpose_half<<<dim3(ADIMD/32, ADIMD/32), tb>>>(Wp + (size_t)i*ADIMD*ADIMD, Wpt + (size_t)i*ADIMD*ADIMD, ADIMD, ADIMD);
        transpose_half<<<dim3(DIMD/32, ADIMD/32), tb>>>(Wf + (size_t)i*ADIMD*DIMD, Wft + (size_t)i*DIMD*ADIMD, ADIMD, DIMD);
        transpose_half<<<dim3(HIDD/32, DIMD/32), tb>>>(W1 + (size_t)i*DIMD*HIDD, W1t + (size_t)i*HIDD*DIMD, DIMD, HIDD);
        transpose_half<<<dim3(DIMD/32, HIDD/32), tb>>>(W2 + (size_t)i*HIDD*DIMD, W2t + (size_t)i*DIMD*HIDD, HIDD, DIMD);
    }

    const dim3 gQK (ADIMD / 128, MROWS / 128);
    const dim3 gDIM(DIMD  / 128, MROWS / 128);
    const dim3 gHID(HIDD  / 128, MROWS / 128);

    for (int i = 0; i < DEPTH; i++) {
        const __half* Wqt_i = Wqt + (size_t)i * ADIMD * DIMD;
        const __half* Wkt_i = Wkt + (size_t)i * ADIMD * DIMD;
        const __half* Wpt_i = Wpt + (size_t)i * ADIMD * ADIMD;
        const __half* Wft_i = Wft + (size_t)i * DIMD * ADIMD;
        const __half* W1t_i = W1t + (size_t)i * HIDD * DIMD;
        const __half* W2t_i = W2t + (size_t)i * DIMD * HIDD;

        ln_kernel<<<MROWS, 256>>>(x, ln1_g + i * DIMD, ln1_b + i * DIMD, h);
        hgemm<0><<<gQK, 256, SMEM_HGEMM>>>(ADIMD, DIMD, h, Wqt_i, bq + i * ADIMD, nullptr, q);
        hgemm<0><<<gQK, 256, SMEM_HGEMM>>>(ADIMD, DIMD, h, Wkt_i, bk + i * ADIMD, nullptr, k);
        rownorm_kernel<<<MROWS / 8, 256>>>(q);
        rownorm_kernel<<<MROWS / 8, 256>>>(k);
        adot_kernel<<<MROWS / 8, 256>>>(q, w_g + i * ADIMD, a);
        anorm_kernel<<<NB, 256>>>(a, rn);
        gsum1_kernel<<<NB * 32, ADIMD>>>(q, a, Gp);
        gsum2_kernel<<<NB, ADIMD>>>(Gp, rn, G);
        kscale_kernel<<<(MROWS * ADIMD / 2) / 1024, 1024>>>(k, G);
        hgemm<3><<<gQK, 256, SMEM_HGEMM>>>(ADIMD, ADIMD, k, Wpt_i, bp + i * ADIMD, q, att);
        hgemm<1><<<gDIM, 256, SMEM_HGEMM>>>(DIMD, ADIMD, att, Wft_i, bf + i * DIMD, nullptr, x);
        ln_kernel<<<MROWS, 256>>>(x, ln2_g + i * DIMD, ln2_b + i * DIMD, h);
        hgemm<2><<<gHID, 256, SMEM_HGEMM>>>(HIDD, DIMD, h, W1t_i, b1 + i * HIDD, nullptr, hid);
        hgemm<1><<<gDIM, 256, SMEM_HGEMM>>>(DIMD, HIDD, hid, W2t_i, b2 + i * DIMD, nullptr, x);
    }
}